// round 14
// baseline (speedup 1.0000x reference)
#include <cuda_runtime.h>
#include <stdint.h>

// ModSTDP: bit-exact jax.random threefry2x32 (partitionable scheme, verified
// rel_err=0.0) + 4-branch STDP update, block-compacted rare draws.
// R14 = R6 resubmit (broker timeouts; this variant has never run).
// R6: occupancy fix (launch_bounds 256,6: 48->40 regs, 5->6 CTAs/SM),
//     smem LUT for (k0,k1,th) select (1 conflict-free LDS.128 vs ~6 SEL),
//     plus = br&1 trick, final apply re-reads w from smem.

constexpr uint32_t NNEUR = 2048;
constexpr uint32_t NSYN  = 8192;
constexpr uint32_t TOT   = NNEUR * NSYN;   // 2^24

constexpr int BT  = 256;        // threads per block
constexpr int EPT = 8;          // elements per thread (contiguous)
constexpr int BE  = BT * EPT;   // 2048 elements per block

// ---------------- compile-time threefry2x32 (key derivation) ----------------
struct P2 { uint32_t a, b; };
constexpr uint32_t rotl_c(uint32_t x, int r) { return (x << r) | (x >> (32 - r)); }

constexpr P2 tf_c(uint32_t k0, uint32_t k1, uint32_t c0, uint32_t c1) {
  uint32_t k2 = k0 ^ k1 ^ 0x1BD11BDAu;
  uint32_t x0 = c0 + k0, x1 = c1 + k1;
  int RA[4] = {13, 15, 26, 6};
  int RB[4] = {17, 29, 16, 24};
  for (int i = 0; i < 4; i++) { x0 += x1; x1 = rotl_c(x1, RA[i]); x1 ^= x0; }
  x0 += k1; x1 += k2 + 1u;
  for (int i = 0; i < 4; i++) { x0 += x1; x1 = rotl_c(x1, RB[i]); x1 ^= x0; }
  x0 += k2; x1 += k0 + 2u;
  for (int i = 0; i < 4; i++) { x0 += x1; x1 = rotl_c(x1, RA[i]); x1 ^= x0; }
  x0 += k0; x1 += k1 + 3u;
  for (int i = 0; i < 4; i++) { x0 += x1; x1 = rotl_c(x1, RB[i]); x1 ^= x0; }
  x0 += k1; x1 += k2 + 4u;
  for (int i = 0; i < 4; i++) { x0 += x1; x1 = rotl_c(x1, RA[i]); x1 ^= x0; }
  x0 += k2; x1 += k0 + 5u;
  return P2{x0, x1};
}

// master key (0,42); rk[i]=tf((0,42),(0,i)).
// rk0 fplus, rk1 fminus, rk2 ucap, rk3 uminus, rk4 usearch, rk5 ubackoff,
// rk6 umin1; split(rk7,3) -> umin2, umin3, umin4.
constexpr P2 RK7_ = tf_c(0u, 42u, 0u, 7u);
constexpr uint32_t RK0a = tf_c(0u,42u,0u,0u).a, RK0b = tf_c(0u,42u,0u,0u).b;
constexpr uint32_t RK1a = tf_c(0u,42u,0u,1u).a, RK1b = tf_c(0u,42u,0u,1u).b;
constexpr uint32_t RK2a = tf_c(0u,42u,0u,2u).a, RK2b = tf_c(0u,42u,0u,2u).b;
constexpr uint32_t RK3a = tf_c(0u,42u,0u,3u).a, RK3b = tf_c(0u,42u,0u,3u).b;
constexpr uint32_t RK4a = tf_c(0u,42u,0u,4u).a, RK4b = tf_c(0u,42u,0u,4u).b;
constexpr uint32_t RK5a = tf_c(0u,42u,0u,5u).a, RK5b = tf_c(0u,42u,0u,5u).b;
constexpr uint32_t RK6a = tf_c(0u,42u,0u,6u).a, RK6b = tf_c(0u,42u,0u,6u).b;
constexpr uint32_t K7Aa = tf_c(RK7_.a,RK7_.b,0u,0u).a, K7Ab = tf_c(RK7_.a,RK7_.b,0u,0u).b;
constexpr uint32_t K7Ba = tf_c(RK7_.a,RK7_.b,0u,1u).a, K7Bb = tf_c(RK7_.a,RK7_.b,0u,1u).b;
constexpr uint32_t K7Ca = tf_c(RK7_.a,RK7_.b,0u,2u).a, K7Cb = tf_c(RK7_.a,RK7_.b,0u,2u).b;

// u-draw thresholds, pre-shifted: u01(bits) < k/128  <=>  bits < (k/128 * 2^23)<<9
constexpr uint32_t TH_CAP  = 655360u  << 9;  // 10/128 (capture & minus)
constexpr uint32_t TH_SRCH = 65536u   << 9;  // 1/128
constexpr uint32_t TH_BACK = 6291456u << 9;  // 96/128
constexpr uint32_t TH_UMIN = 262144u  << 9;  // 4/128

// ---------------- device threefry ----------------
__device__ __forceinline__ uint32_t tf_bits(uint32_t k0, uint32_t k1, uint32_t e) {
  uint32_t k2 = k0 ^ k1 ^ 0x1BD11BDAu;
  uint32_t x0 = k0;          // hi counter = 0
  uint32_t x1 = e + k1;      // lo counter = e
#define R_(r) { x0 += x1; x1 = __funnelshift_l(x1, x1, (r)); x1 ^= x0; }
  R_(13) R_(15) R_(26) R_(6)
  x0 += k1; x1 += k2 + 1u;
  R_(17) R_(29) R_(16) R_(24)
  x0 += k2; x1 += k0 + 2u;
  R_(13) R_(15) R_(26) R_(6)
  x0 += k0; x1 += k1 + 3u;
  R_(17) R_(29) R_(16) R_(24)
  x0 += k1; x1 += k2 + 4u;
  R_(13) R_(15) R_(26) R_(6)
  x0 += k2; x1 += k0 + 5u;
#undef R_
  return x0 ^ x1;
}

// ---------------- main kernel ----------------
__global__ void __launch_bounds__(BT, 6) modstdp_kernel(
    const int* __restrict__ ispk,     // [8, N, S]
    const int* __restrict__ ospk,     // [8, N]
    const float* __restrict__ W,      // [N, S]
    float* __restrict__ out)          // [N, S]
{
  __shared__ float    sw[BE];                    // clamped weights (8KB)
  __shared__ uint16_t q1[BE];                    // u-survivors: (lidx<<2)|(br-1)
  __shared__ uint16_t q2[BE];                    // u & !f survivors
  __shared__ __align__(8) uint8_t sd[BE];        // delta flag per element (2KB)
  __shared__ uint4    klut[5];                   // (k0, k1, th, 0) per br
  __shared__ int      cnt1, cnt2;

  const uint32_t tid  = threadIdx.x;
  const uint32_t base = blockIdx.x * (uint32_t)BE;
  const uint32_t e0   = base + tid * EPT;        // 8 contiguous elements

  if (tid == 0) { cnt1 = 0; cnt2 = 0; }
  if (tid < 5) {
    // br=0 row: th=0 -> compare always false, draw harmlessly discarded
    const uint4 rows[5] = {
      make_uint4(0u,   0u,   0u,      0u),
      make_uint4(RK2a, RK2b, TH_CAP,  0u),   // capture
      make_uint4(RK3a, RK3b, TH_CAP,  0u),   // minus
      make_uint4(RK4a, RK4b, TH_SRCH, 0u),   // search
      make_uint4(RK5a, RK5b, TH_BACK, 0u),   // backoff
    };
    klut[tid] = rows[tid];
  }
  *reinterpret_cast<uint64_t*>(&sd[tid * EPT]) = 0ull;   // zero my 8 flags

  // ---- spike-count sum over T=8 (vectorized int4 loads) ----
  int s[EPT];
#pragma unroll
  for (int i = 0; i < EPT; i++) s[i] = 0;
#pragma unroll
  for (int t = 0; t < 8; t++) {
    const int4* p = reinterpret_cast<const int4*>(ispk + (size_t)t * TOT + e0);
    int4 a = __ldg(p), b = __ldg(p + 1);
    s[0] += a.x; s[1] += a.y; s[2] += a.z; s[3] += a.w;
    s[4] += b.x; s[5] += b.y; s[6] += b.z; s[7] += b.w;
  }

  // ---- out-spike sum: neuron is block-uniform (BE=2048 divides S=8192) ----
  const uint32_t n = base >> 13;
  int so = 0;
#pragma unroll
  for (int t = 0; t < 8; t++) so += __ldg(ospk + t * NNEUR + n);
  const bool ouf = so > 0;                       // out fired
  // it <= ot  <=>  8-s <= 8-so  <=>  s >= so

  // ---- weights (2x float4), clamp, stage to smem (not kept in regs) ----
  {
    const float4* p = reinterpret_cast<const float4*>(W + e0);
    float4 a = __ldg(p), b = __ldg(p + 1);
    float* d = &sw[tid * EPT];
    d[0] = fminf(fmaxf(a.x, 0.0f), 8.0f);
    d[1] = fminf(fmaxf(a.y, 0.0f), 8.0f);
    d[2] = fminf(fmaxf(a.z, 0.0f), 8.0f);
    d[3] = fminf(fmaxf(a.w, 0.0f), 8.0f);
    d[4] = fminf(fmaxf(b.x, 0.0f), 8.0f);
    d[5] = fminf(fmaxf(b.y, 0.0f), 8.0f);
    d[6] = fminf(fmaxf(b.z, 0.0f), 8.0f);
    d[7] = fminf(fmaxf(b.w, 0.0f), 8.0f);
  }
  __syncthreads();   // sd zeroed + sw + klut + cnt visible

  // ---- phase 1: mandatory u-draw per element; push survivors ----
  uint32_t umask = 0, plusmask = 0;
#pragma unroll
  for (int i = 0; i < EPT; i++) {
    const bool inf = s[i] > 0;
    // br: 1 capture(+), 2 minus(-), 3 search(+), 4 backoff(-), 0 none
    const int br = (inf & ouf) ? ((s[i] >= so) ? 1 : 2)
                               : (inf ? 3 : (ouf ? 4 : 0));
    plusmask |= (uint32_t)(br & 1) << i;         // plus <=> br odd (1 or 3)

    const uint4 kt = klut[br];                   // LDS.128, conflict-free
    const uint32_t bits = tf_bits(kt.x, kt.y, e0 + i);
    if (bits < kt.z) {                           // th=0 for br==0
      umask |= 1u << i;
      const int slot = atomicAdd(&cnt1, 1);      // warp-aggregated by ptxas
      q1[slot] = (uint16_t)(((tid * EPT + i) << 2) | (br - 1));
    }
  }
  __syncthreads();

  // ---- phase 2: f-draw only for u-survivors (~8%) ----
  const int c1 = cnt1;
  for (int k = tid; k < c1; k += BT) {
    const uint32_t ent  = q1[k];
    const uint32_t lidx = ent >> 2;
    const uint32_t brm  = ent & 3;               // br-1
    const bool plus = !(brm & 1);                // brm 0,2 -> plus
    const float w_  = sw[lidx];
    const float wn  = w_ * 0.125f;
    const float pf  = plus ? (wn * (2.0f - wn)) : ((1.0f - wn) * (1.0f + wn));
    const uint32_t bits = tf_bits(plus ? RK0a : RK1a, plus ? RK0b : RK1b,
                                  base + lidx);
    const float uu = (float)(bits >> 9) * 0x1p-23f;   // == JAX uniform exactly
    if (uu < pf) {
      sd[lidx] = 1;
    } else {
      const int slot = atomicAdd(&cnt2, 1);
      q2[slot] = (uint16_t)ent;
    }
  }
  __syncthreads();

  // ---- phase 3: umin-draw only for u & !f survivors (~2.6%) ----
  const int c2 = cnt2;
  for (int k = tid; k < c2; k += BT) {
    const uint32_t ent  = q2[k];
    const uint32_t lidx = ent >> 2;
    const uint32_t brm  = ent & 3;
    // umin keys: br1->rk6, br2->k7a, br3->k7b, br4->k7c
    const uint32_t k0 = (brm <= 1) ? ((brm == 0) ? RK6a : K7Aa)
                                   : ((brm == 2) ? K7Ba : K7Ca);
    const uint32_t k1 = (brm <= 1) ? ((brm == 0) ? RK6b : K7Ab)
                                   : ((brm == 2) ? K7Bb : K7Cb);
    if (tf_bits(k0, k1, base + lidx) < TH_UMIN) sd[lidx] = 1;
  }
  __syncthreads();

  // ---- final: apply deltas (w re-read from smem), vectorized store ----
  const float4 wa = *reinterpret_cast<const float4*>(&sw[tid * EPT]);
  const float4 wb = *reinterpret_cast<const float4*>(&sw[tid * EPT + 4]);
  const float wv[EPT] = {wa.x, wa.y, wa.z, wa.w, wb.x, wb.y, wb.z, wb.w};
  float r[EPT];
#pragma unroll
  for (int i = 0; i < EPT; i++) {
    const float d = (umask >> i & 1u) ? (float)sd[tid * EPT + i] : 0.0f;
    r[i] = (plusmask >> i & 1u) ? (wv[i] + d) : (wv[i] - d);
  }
  float4* po = reinterpret_cast<float4*>(out + e0);
  po[0] = make_float4(r[0], r[1], r[2], r[3]);
  po[1] = make_float4(r[4], r[5], r[6], r[7]);
}

extern "C" void kernel_launch(void* const* d_in, const int* in_sizes, int n_in,
                              void* d_out, int out_size) {
  (void)in_sizes; (void)n_in; (void)out_size;
  const int*   ispk = (const int*)d_in[0];
  const int*   ospk = (const int*)d_in[1];
  const float* W    = (const float*)d_in[2];
  float*       out  = (float*)d_out;
  modstdp_kernel<<<TOT / BE, BT>>>(ispk, ospk, W, out);
}